// round 13
// baseline (speedup 1.0000x reference)
#include <cuda_runtime.h>
#include <math.h>

#define B_ 8
#define H_ 256
#define W_ 256
#define C_ 128
#define HW_ (H_ * W_)          // 65536
#define P_ (B_ * HW_)          // 524288 pixels
#define NBLK_ 128              // chunks per batch (512 px = 2 rows each)
#define PBLK_ 64               // pixels per pool block
#define THRESH_ 0.8f
#define EPS_ 1e-3f

// ---- scratch (device globals; no allocation allowed) ----
__device__ float g_pooled[P_ * 2];                 // 4 MB
__device__ float g_gmap[P_];                       // 2 MB
__device__ float g_bmap[P_];                       // 2 MB
__device__ unsigned char g_mask[P_];               // 0.5 MB
__device__ int   g_counts[B_];
__device__ int   g_done[B_];
__device__ float4 g_tot1[(P_ / PBLK_) * 32];       // per-pool-block S1  (4 MB)
__device__ float4 g_tot2[(P_ / PBLK_) * 32];       // per-pool-block S2  (4 MB)
__device__ float4 g_partials[B_ * NBLK_ * C_];     // {s1v,s2v,s1,s2}    2 MB
__device__ float g_params[B_ * 2 * C_ * 2];        // 8 KB

// ============================================================
// Kernel 1: channel max/avg pool + per-block unmasked S1/S2 totals.
// ============================================================
__global__ void pool_kernel(const float* __restrict__ in) {
    if (blockIdx.x == 0 && threadIdx.x < B_) {
        g_counts[threadIdx.x] = 0;
        g_done[threadIdx.x] = 0;
    }

    int t = threadIdx.x;
    int warp = t >> 5, lane = t & 31;
    int pix0 = blockIdx.x * PBLK_ + warp * 8;
    const float4* p = (const float4*)in;

    float4 v[8];
    #pragma unroll
    for (int k = 0; k < 8; k++)
        v[k] = p[(size_t)(pix0 + k) * 32 + lane];

    float mx[8], sm[8];
    float4 s1 = make_float4(0,0,0,0), s2 = make_float4(0,0,0,0);
    #pragma unroll
    for (int k = 0; k < 8; k++) {
        mx[k] = fmaxf(fmaxf(v[k].x, v[k].y), fmaxf(v[k].z, v[k].w));
        sm[k] = (v[k].x + v[k].y) + (v[k].z + v[k].w);
        s1.x += v[k].x;            s1.y += v[k].y;
        s1.z += v[k].z;            s1.w += v[k].w;
        s2.x += v[k].x * v[k].x;   s2.y += v[k].y * v[k].y;
        s2.z += v[k].z * v[k].z;   s2.w += v[k].w * v[k].w;
    }

    // value-halving reduction
    #pragma unroll
    for (int k = 0; k < 4; k++) {
        float mlo = __shfl_xor_sync(0xFFFFFFFFu, mx[k], 16);
        float mhi = __shfl_xor_sync(0xFFFFFFFFu, mx[k + 4], 16);
        float slo = __shfl_xor_sync(0xFFFFFFFFu, sm[k], 16);
        float shi = __shfl_xor_sync(0xFFFFFFFFu, sm[k + 4], 16);
        if (lane & 16) { mx[k] = fmaxf(mx[k + 4], mhi); sm[k] = sm[k + 4] + shi; }
        else           { mx[k] = fmaxf(mx[k],     mlo); sm[k] = sm[k]     + slo; }
    }
    #pragma unroll
    for (int k = 0; k < 2; k++) {
        float mlo = __shfl_xor_sync(0xFFFFFFFFu, mx[k], 8);
        float mhi = __shfl_xor_sync(0xFFFFFFFFu, mx[k + 2], 8);
        float slo = __shfl_xor_sync(0xFFFFFFFFu, sm[k], 8);
        float shi = __shfl_xor_sync(0xFFFFFFFFu, sm[k + 2], 8);
        if (lane & 8) { mx[k] = fmaxf(mx[k + 2], mhi); sm[k] = sm[k + 2] + shi; }
        else          { mx[k] = fmaxf(mx[k],     mlo); sm[k] = sm[k]     + slo; }
    }
    {
        float mlo = __shfl_xor_sync(0xFFFFFFFFu, mx[0], 4);
        float mhi = __shfl_xor_sync(0xFFFFFFFFu, mx[1], 4);
        float slo = __shfl_xor_sync(0xFFFFFFFFu, sm[0], 4);
        float shi = __shfl_xor_sync(0xFFFFFFFFu, sm[1], 4);
        if (lane & 4) { mx[0] = fmaxf(mx[1], mhi); sm[0] = sm[1] + shi; }
        else          { mx[0] = fmaxf(mx[0], mlo); sm[0] = sm[0] + slo; }
    }
    mx[0] = fmaxf(mx[0], __shfl_xor_sync(0xFFFFFFFFu, mx[0], 2));
    sm[0] += __shfl_xor_sync(0xFFFFFFFFu, sm[0], 2);
    mx[0] = fmaxf(mx[0], __shfl_xor_sync(0xFFFFFFFFu, mx[0], 1));
    sm[0] += __shfl_xor_sync(0xFFFFFFFFu, sm[0], 1);

    if ((lane & 3) == 0) {
        int pixk = ((lane & 16) ? 4 : 0) + ((lane & 8) ? 2 : 0) + ((lane & 4) ? 1 : 0);
        float2 r; r.x = mx[0]; r.y = sm[0] * (1.0f / (float)C_);
        ((float2*)g_pooled)[pix0 + pixk] = r;
    }

    __shared__ float4 sm1[8][32], sm2[8][32];
    sm1[warp][lane] = s1;
    sm2[warp][lane] = s2;
    __syncthreads();
    if (t < 32) {
        float4 a = make_float4(0,0,0,0);
        #pragma unroll
        for (int w = 0; w < 8; w++) {
            float4 x = sm1[w][t];
            a.x += x.x; a.y += x.y; a.z += x.z; a.w += x.w;
        }
        g_tot1[blockIdx.x * 32 + t] = a;
    } else if (t < 64) {
        int c = t - 32;
        float4 a = make_float4(0,0,0,0);
        #pragma unroll
        for (int w = 0; w < 8; w++) {
            float4 x = sm2[w][c];
            a.x += x.x; a.y += x.y; a.z += x.z; a.w += x.w;
        }
        g_tot2[blockIdx.x * 32 + c] = a;
    }
}

// ============================================================
// Kernel 2: FUSED moments+conv. Block = 2 image rows (512 px).
//  a) conv: pooled 6x258 halo -> xmap 4x258 -> mask/gamma/beta + count
//  b) per-warp min-region compaction + gather (warp = 64 px = 1 pool block)
//  c) per-chunk partials; last block of batch finalizes mu/invstd
// ============================================================
__global__ void moments_kernel(const float* __restrict__ in,
                               const float* __restrict__ w_sr,
                               const float* __restrict__ b_sr,
                               const float* __restrict__ w_g,
                               const float* __restrict__ b_g,
                               const float* __restrict__ w_b,
                               const float* __restrict__ b_b) {
    int r  = blockIdx.x;                 // 2-row group 0..127
    int b  = (B_ - 1) - blockIdx.y;      // reverse batch order
    int t  = threadIdx.x;
    int warp = t >> 5, lane = t & 31;
    int cbase = b * HW_ + r * 512;
    int bbase = b << 16;
    int row0  = r * 2;

    __shared__ float2 sp[6][258];
    __shared__ float  xm[4][258];
    __shared__ float  swsr[18], swg[9], swb[9], sbias[3];
    __shared__ unsigned char sflag[512];
    __shared__ unsigned short slist[512];
    __shared__ int scnt1[8];
    __shared__ float4 r1[256], r2[256];
    __shared__ float4 st1[8][32], st2[8][32];
    __shared__ float4 ssel1[32], ssel2[32], stot1[32], stot2[32];

    if (t < 18) swsr[t] = w_sr[t];
    if (t < 9) { swg[t] = w_g[t]; swb[t] = w_b[t]; }
    if (t == 0) { sbias[0] = b_sr[0]; sbias[1] = b_g[0]; sbias[2] = b_b[0]; }

    // ---- (a1) pooled halo: rows row0-2..row0+3, cols -1..256 ----
    const float2* pooled2 = (const float2*)g_pooled;
    for (int l = t; l < 6 * 258; l += 256) {
        int i = l / 258, j = l % 258;
        int gr = row0 - 2 + i, col = j - 1;
        float2 val = make_float2(0.f, 0.f);
        if (gr >= 0 && gr < H_ && col >= 0 && col < W_)
            val = pooled2[bbase + (gr << 8) + col];
        sp[i][j] = val;
    }
    __syncthreads();

    // ---- (a2) xmap rows row0-1..row0+2 (zero outside image) ----
    for (int l = t; l < 4 * 258; l += 256) {
        int i = l / 258, j = l % 258;
        int gr = row0 - 1 + i, col = j - 1;
        float x = 0.f;
        if (gr >= 0 && gr < H_ && col >= 0 && col < W_) {
            float acc = sbias[0];
            #pragma unroll
            for (int kh = 0; kh < 3; kh++)
                #pragma unroll
                for (int kw = 0; kw < 3; kw++) {
                    float2 pv = sp[i + kh][j - 1 + kw];
                    acc += pv.x * swsr[(kh * 3 + kw) * 2]
                         + pv.y * swsr[(kh * 3 + kw) * 2 + 1];
                }
            x = 1.0f / (1.0f + __expf(-acc));
        }
        xm[i][j] = x;
    }
    __syncthreads();

    // ---- (a3) mask / gamma / beta for the 512 center pixels ----
    #pragma unroll
    for (int k = 0; k < 2; k++) {
        int idx = t + k * 256;
        int i  = idx >> 8;        // 0 or 1
        int cc = idx & 255;
        float gg = sbias[1], bbv = sbias[2];
        #pragma unroll
        for (int kh = 0; kh < 3; kh++)
            #pragma unroll
            for (int kw = 0; kw < 3; kw++) {
                float xv = xm[i + kh][cc + kw];
                gg  += xv * swg[kh * 3 + kw];
                bbv += xv * swb[kh * 3 + kw];
            }
        float x = xm[i + 1][cc + 1];
        unsigned char m = (x > THRESH_) ? 1 : 0;
        int pixel = cbase + idx;
        g_mask[pixel] = m;
        g_gmap[pixel] = gg;
        g_bmap[pixel] = bbv;
        sflag[idx] = m;
    }
    __syncthreads();

    // ---- (b) per-warp min-region selection + compaction ----
    int base_px = warp * 64;
    int f0 = sflag[base_px + lane];
    int f1 = sflag[base_px + 32 + lane];
    unsigned bal0 = __ballot_sync(0xFFFFFFFFu, f0);
    unsigned bal1 = __ballot_sync(0xFFFFFFFFu, f1);
    int ones = __popc(bal0) + __popc(bal1);
    if (lane == 0) scnt1[warp] = ones;
    int selb = (ones <= 32) ? 1 : 0;
    unsigned sb0 = selb ? bal0 : ~bal0;
    unsigned sb1 = selb ? bal1 : ~bal1;
    int n0 = __popc(sb0);
    int nselw = n0 + __popc(sb1);
    unsigned lmask = (1u << lane) - 1u;
    if ((sb0 >> lane) & 1) slist[base_px + __popc(sb0 & lmask)] = (unsigned short)(base_px + lane);
    if ((sb1 >> lane) & 1) slist[base_px + n0 + __popc(sb1 & lmask)] = (unsigned short)(base_px + 32 + lane);
    __syncwarp();

    // gather own warp's list, MLP=4
    const float4* basep = ((const float4*)in) + (size_t)cbase * 32 + lane;
    float4 a1 = make_float4(0,0,0,0), a2 = make_float4(0,0,0,0);
    int i2 = 0;
    for (; i2 + 3 < nselw; i2 += 4) {
        int p0 = slist[base_px + i2];
        int p1 = slist[base_px + i2 + 1];
        int p2 = slist[base_px + i2 + 2];
        int p3 = slist[base_px + i2 + 3];
        float4 v0 = basep[(size_t)p0 * 32];
        float4 v1 = basep[(size_t)p1 * 32];
        float4 v2 = basep[(size_t)p2 * 32];
        float4 v3 = basep[(size_t)p3 * 32];
        a1.x += v0.x; a1.y += v0.y; a1.z += v0.z; a1.w += v0.w;
        a2.x += v0.x * v0.x; a2.y += v0.y * v0.y; a2.z += v0.z * v0.z; a2.w += v0.w * v0.w;
        a1.x += v1.x; a1.y += v1.y; a1.z += v1.z; a1.w += v1.w;
        a2.x += v1.x * v1.x; a2.y += v1.y * v1.y; a2.z += v1.z * v1.z; a2.w += v1.w * v1.w;
        a1.x += v2.x; a1.y += v2.y; a1.z += v2.z; a1.w += v2.w;
        a2.x += v2.x * v2.x; a2.y += v2.y * v2.y; a2.z += v2.z * v2.z; a2.w += v2.w * v2.w;
        a1.x += v3.x; a1.y += v3.y; a1.z += v3.z; a1.w += v3.w;
        a2.x += v3.x * v3.x; a2.y += v3.y * v3.y; a2.z += v3.z * v3.z; a2.w += v3.w * v3.w;
    }
    for (; i2 < nselw; i2++) {
        int p = slist[base_px + i2];
        float4 v = basep[(size_t)p * 32];
        a1.x += v.x; a1.y += v.y; a1.z += v.z; a1.w += v.w;
        a2.x += v.x * v.x; a2.y += v.y * v.y; a2.z += v.z * v.z; a2.w += v.w * v.w;
    }

    // per-warp totals (pool-block aligned with this warp's 64 px)
    int pb = (cbase >> 6) + warp;
    float4 tw1 = g_tot1[pb * 32 + lane];
    float4 tw2 = g_tot2[pb * 32 + lane];
    float4 s1v, s2v;
    s1v.x = selb ? a1.x : (tw1.x - a1.x);
    s1v.y = selb ? a1.y : (tw1.y - a1.y);
    s1v.z = selb ? a1.z : (tw1.z - a1.z);
    s1v.w = selb ? a1.w : (tw1.w - a1.w);
    s2v.x = selb ? a2.x : (tw2.x - a2.x);
    s2v.y = selb ? a2.y : (tw2.y - a2.y);
    s2v.z = selb ? a2.z : (tw2.z - a2.z);
    s2v.w = selb ? a2.w : (tw2.w - a2.w);

    r1[t] = s1v; r2[t] = s2v;
    st1[warp][lane] = tw1; st2[warp][lane] = tw2;
    __syncthreads();

    // 4-way parallel 8-warp reductions
    if (t < 32) {
        float4 a = make_float4(0,0,0,0);
        #pragma unroll
        for (int w = 0; w < 8; w++) {
            float4 x = r1[w * 32 + t];
            a.x += x.x; a.y += x.y; a.z += x.z; a.w += x.w;
        }
        ssel1[t] = a;
    } else if (t < 64) {
        int c = t - 32;
        float4 a = make_float4(0,0,0,0);
        #pragma unroll
        for (int w = 0; w < 8; w++) {
            float4 x = r2[w * 32 + c];
            a.x += x.x; a.y += x.y; a.z += x.z; a.w += x.w;
        }
        ssel2[c] = a;
    } else if (t < 96) {
        int c = t - 64;
        float4 a = make_float4(0,0,0,0);
        #pragma unroll
        for (int w = 0; w < 8; w++) {
            float4 x = st1[w][c];
            a.x += x.x; a.y += x.y; a.z += x.z; a.w += x.w;
        }
        stot1[c] = a;
    } else if (t < 128) {
        int c = t - 96;
        float4 a = make_float4(0,0,0,0);
        #pragma unroll
        for (int w = 0; w < 8; w++) {
            float4 x = st2[w][c];
            a.x += x.x; a.y += x.y; a.z += x.z; a.w += x.w;
        }
        stot2[c] = a;
    }
    __syncthreads();

    // per-chunk partials: {s1v, s2v, s1tot, s2tot} per channel
    if (t < C_) {
        int c4 = t >> 2, k = t & 3;
        g_partials[((size_t)b * NBLK_ + r) * C_ + t] = make_float4(
            ((const float*)&ssel1[c4])[k],
            ((const float*)&ssel2[c4])[k],
            ((const float*)&stot1[c4])[k],
            ((const float*)&stot2[c4])[k]);
    }

    // mask count for this chunk
    if (t == 0) {
        int s = 0;
        #pragma unroll
        for (int w = 0; w < 8; w++) s += scnt1[w];
        atomicAdd(&g_counts[b], s);
    }

    // ---- (c) last block of this batch finalizes ----
    __shared__ int is_last;
    __threadfence();
    __syncthreads();
    if (t == 0) is_last = (atomicAdd(&g_done[b], 1) == NBLK_ - 1) ? 1 : 0;
    __syncthreads();
    if (!is_last) return;

    {
        int c    = t & 127;
        int half = t >> 7;
        const float4* pp = g_partials + (size_t)b * NBLK_ * C_ + (size_t)(half * 64) * C_ + c;
        float a1s = 0.f, a2s = 0.f, a3s = 0.f, a4s = 0.f;
        #pragma unroll 8
        for (int k = 0; k < 64; k++) {
            float4 p = pp[(size_t)k * C_];
            a1s += p.x; a2s += p.y; a3s += p.z; a4s += p.w;
        }
        r1[t] = make_float4(a1s, a2s, a3s, a4s);
    }
    __syncthreads();
    if (t < C_) {
        float4 lo = r1[t], hi = r1[t + 128];
        float s1v_ = lo.x + hi.x;
        float s2v_ = lo.y + hi.y;
        float s1_  = lo.z + hi.z;
        float s2_  = lo.w + hi.w;

        float cnt_v = (float)g_counts[b];
        float cnt_m = (float)HW_ - cnt_v;
        float s1m = s1_ - s1v_;
        float s2m = s2_ - s2v_;

        float fs_v  = cnt_v + EPS_;
        float mu_v  = s1v_ / fs_v;
        float var_v = (s2v_ - 2.f * mu_v * s1v_ + mu_v * mu_v * cnt_v) / fs_v;
        float is_v  = 1.0f / sqrtf(var_v + EPS_);
        float fs_m  = cnt_m + EPS_;
        float mu_m  = s1m / fs_m;
        float var_m = (s2m - 2.f * mu_m * s1m + mu_m * mu_m * cnt_m) / fs_m;
        float is_m  = 1.0f / sqrtf(var_m + EPS_);

        ((float2*)g_params)[((size_t)b * 2 + 1) * C_ + t] = make_float2(mu_v, is_v);
        ((float2*)g_params)[((size_t)b * 2 + 0) * C_ + t] = make_float2(mu_m, is_m);
    }
}

// ============================================================
// Kernel 3: apply — R4-identical smem-params version (32 regs, occ 88%).
// ============================================================
__global__ void apply_kernel(const float* __restrict__ in, float* __restrict__ out) {
    int t = threadIdx.x;
    size_t base = (size_t)blockIdx.x * 1024;
    int pix0 = blockIdx.x * 32;
    int b = pix0 >> 16;

    __shared__ float4 sparams[128];   // [region(2)][c4(32)][2]
    if (t < 128) sparams[t] = ((const float4*)g_params)[b * 128 + t];
    __syncthreads();

    const float4* in4 = (const float4*)in;
    float4* out4 = (float4*)out;

    float4 v[4];
    #pragma unroll
    for (int k = 0; k < 4; k++)
        v[k] = in4[base + t + 256 * k];

    #pragma unroll
    for (int k = 0; k < 4; k++) {
        int i4  = t + 256 * k;
        int pix = pix0 + (i4 >> 5);
        int c4  = i4 & 31;
        int m        = g_mask[pix];
        float beta   = g_bmap[pix];
        float gamma  = g_gmap[pix];
        float4 p0 = sparams[m * 64 + c4 * 2];
        float4 p1 = sparams[m * 64 + c4 * 2 + 1];
        float4 o;
        o.x = (v[k].x - p0.x) * p0.y * beta + gamma;
        o.y = (v[k].y - p0.z) * p0.w * beta + gamma;
        o.z = (v[k].z - p1.x) * p1.y * beta + gamma;
        o.w = (v[k].w - p1.z) * p1.w * beta + gamma;
        out4[base + i4] = o;
    }
}

// ============================================================
extern "C" void kernel_launch(void* const* d_in, const int* in_sizes, int n_in,
                              void* d_out, int out_size) {
    const float* in      = (const float*)d_in[0];
    const float* w_sr    = (const float*)d_in[1];
    const float* b_sr    = (const float*)d_in[2];
    const float* w_gamma = (const float*)d_in[3];
    const float* b_gamma = (const float*)d_in[4];
    const float* w_beta  = (const float*)d_in[5];
    const float* b_beta  = (const float*)d_in[6];
    float* out = (float*)d_out;

    pool_kernel<<<P_ / PBLK_, 256>>>(in);
    moments_kernel<<<dim3(NBLK_, B_), 256>>>(in, w_sr, b_sr,
                                             w_gamma, b_gamma, w_beta, b_beta);
    apply_kernel<<<P_ / 32, 256>>>(in, out);
}

// round 14
// speedup vs baseline: 1.0150x; 1.0150x over previous
#include <cuda_runtime.h>
#include <math.h>

#define B_ 8
#define H_ 256
#define W_ 256
#define C_ 128
#define HW_ (H_ * W_)          // 65536
#define P_ (B_ * HW_)          // 524288 pixels
#define NBLK_ 128              // chunks per batch (512 px each)
#define PBLK_ 64               // pixels per pool block
#define THRESH_ 0.8f
#define EPS_ 1e-3f

// ---- scratch (device globals; no allocation allowed) ----
__device__ float g_pooled[P_ * 2];                 // 4 MB
__device__ float g_gmap[P_];                       // 2 MB
__device__ float g_bmap[P_];                       // 2 MB
__device__ unsigned char g_mask[P_];               // 0.5 MB
__device__ int   g_counts[B_];
__device__ int   g_done[B_];
__device__ float4 g_tot1[(P_ / PBLK_) * 32];       // per-pool-block S1  (4 MB)
__device__ float4 g_tot2[(P_ / PBLK_) * 32];       // per-pool-block S2  (4 MB)
__device__ float4 g_partials[B_ * NBLK_ * C_];     // {s1v,s2v,s1,s2}    2 MB
__device__ float g_params[B_ * 2 * C_ * 2];        // 8 KB

// ============================================================
// Kernel 1: channel max/avg pool + per-block unmasked S1/S2 totals.
// (measured: 43.4us, 6.47 TB/s, 81.6% DRAM)
// ============================================================
__global__ void pool_kernel(const float* __restrict__ in) {
    if (blockIdx.x == 0 && threadIdx.x < B_) {
        g_counts[threadIdx.x] = 0;
        g_done[threadIdx.x] = 0;
    }

    int t = threadIdx.x;
    int warp = t >> 5, lane = t & 31;
    int pix0 = blockIdx.x * PBLK_ + warp * 8;
    const float4* p = (const float4*)in;

    float4 v[8];
    #pragma unroll
    for (int k = 0; k < 8; k++)
        v[k] = p[(size_t)(pix0 + k) * 32 + lane];

    float mx[8], sm[8];
    float4 s1 = make_float4(0,0,0,0), s2 = make_float4(0,0,0,0);
    #pragma unroll
    for (int k = 0; k < 8; k++) {
        mx[k] = fmaxf(fmaxf(v[k].x, v[k].y), fmaxf(v[k].z, v[k].w));
        sm[k] = (v[k].x + v[k].y) + (v[k].z + v[k].w);
        s1.x += v[k].x;            s1.y += v[k].y;
        s1.z += v[k].z;            s1.w += v[k].w;
        s2.x += v[k].x * v[k].x;   s2.y += v[k].y * v[k].y;
        s2.z += v[k].z * v[k].z;   s2.w += v[k].w * v[k].w;
    }

    // value-halving reduction
    #pragma unroll
    for (int k = 0; k < 4; k++) {
        float mlo = __shfl_xor_sync(0xFFFFFFFFu, mx[k], 16);
        float mhi = __shfl_xor_sync(0xFFFFFFFFu, mx[k + 4], 16);
        float slo = __shfl_xor_sync(0xFFFFFFFFu, sm[k], 16);
        float shi = __shfl_xor_sync(0xFFFFFFFFu, sm[k + 4], 16);
        if (lane & 16) { mx[k] = fmaxf(mx[k + 4], mhi); sm[k] = sm[k + 4] + shi; }
        else           { mx[k] = fmaxf(mx[k],     mlo); sm[k] = sm[k]     + slo; }
    }
    #pragma unroll
    for (int k = 0; k < 2; k++) {
        float mlo = __shfl_xor_sync(0xFFFFFFFFu, mx[k], 8);
        float mhi = __shfl_xor_sync(0xFFFFFFFFu, mx[k + 2], 8);
        float slo = __shfl_xor_sync(0xFFFFFFFFu, sm[k], 8);
        float shi = __shfl_xor_sync(0xFFFFFFFFu, sm[k + 2], 8);
        if (lane & 8) { mx[k] = fmaxf(mx[k + 2], mhi); sm[k] = sm[k + 2] + shi; }
        else          { mx[k] = fmaxf(mx[k],     mlo); sm[k] = sm[k]     + slo; }
    }
    {
        float mlo = __shfl_xor_sync(0xFFFFFFFFu, mx[0], 4);
        float mhi = __shfl_xor_sync(0xFFFFFFFFu, mx[1], 4);
        float slo = __shfl_xor_sync(0xFFFFFFFFu, sm[0], 4);
        float shi = __shfl_xor_sync(0xFFFFFFFFu, sm[1], 4);
        if (lane & 4) { mx[0] = fmaxf(mx[1], mhi); sm[0] = sm[1] + shi; }
        else          { mx[0] = fmaxf(mx[0], mlo); sm[0] = sm[0] + slo; }
    }
    mx[0] = fmaxf(mx[0], __shfl_xor_sync(0xFFFFFFFFu, mx[0], 2));
    sm[0] += __shfl_xor_sync(0xFFFFFFFFu, sm[0], 2);
    mx[0] = fmaxf(mx[0], __shfl_xor_sync(0xFFFFFFFFu, mx[0], 1));
    sm[0] += __shfl_xor_sync(0xFFFFFFFFu, sm[0], 1);

    if ((lane & 3) == 0) {
        int pixk = ((lane & 16) ? 4 : 0) + ((lane & 8) ? 2 : 0) + ((lane & 4) ? 1 : 0);
        float2 r; r.x = mx[0]; r.y = sm[0] * (1.0f / (float)C_);
        ((float2*)g_pooled)[pix0 + pixk] = r;
    }

    __shared__ float4 sm1[8][32], sm2[8][32];
    sm1[warp][lane] = s1;
    sm2[warp][lane] = s2;
    __syncthreads();
    if (t < 32) {
        float4 a = make_float4(0,0,0,0);
        #pragma unroll
        for (int w = 0; w < 8; w++) {
            float4 x = sm1[w][t];
            a.x += x.x; a.y += x.y; a.z += x.z; a.w += x.w;
        }
        g_tot1[blockIdx.x * 32 + t] = a;
    } else if (t < 64) {
        int c = t - 32;
        float4 a = make_float4(0,0,0,0);
        #pragma unroll
        for (int w = 0; w < 8; w++) {
            float4 x = sm2[w][c];
            a.x += x.x; a.y += x.y; a.z += x.z; a.w += x.w;
        }
        g_tot2[blockIdx.x * 32 + c] = a;
    }
}

// ============================================================
// Kernel 2: FUSED conv pipeline (32x32 tiles, 256 threads) — R11 version.
// ============================================================
__global__ void fused_conv_kernel(const float* __restrict__ w_sr,
                                  const float* __restrict__ b_sr,
                                  const float* __restrict__ w_g,
                                  const float* __restrict__ b_g,
                                  const float* __restrict__ w_b,
                                  const float* __restrict__ b_b) {
    __shared__ float2 sp[36][37];
    __shared__ float  xm[34][35];
    __shared__ float  swsr[18], swg[9], swb[9], sbias[3];
    __shared__ int    scnt[8];

    int t = threadIdx.x;
    int b  = blockIdx.x >> 6;
    int tt = blockIdx.x & 63;
    int th = (tt >> 3) << 5;
    int tw = (tt & 7) << 5;
    int bbase = b << 16;

    if (t < 18) swsr[t] = w_sr[t];
    if (t < 9) { swg[t] = w_g[t]; swb[t] = w_b[t]; }
    if (t == 0) { sbias[0] = b_sr[0]; sbias[1] = b_g[0]; sbias[2] = b_b[0]; }

    const float2* pooled2 = (const float2*)g_pooled;
    for (int l = t; l < 36 * 36; l += 256) {
        int i = l / 36, j = l % 36;
        int h = th - 2 + i, w = tw - 2 + j;
        float2 val = make_float2(0.f, 0.f);
        if (h >= 0 && h < H_ && w >= 0 && w < W_)
            val = pooled2[bbase + (h << 8) + w];
        sp[i][j] = val;
    }
    __syncthreads();

    for (int l = t; l < 34 * 34; l += 256) {
        int i = l / 34, j = l % 34;
        int h = th - 1 + i, w = tw - 1 + j;
        float x = 0.f;
        if (h >= 0 && h < H_ && w >= 0 && w < W_) {
            float acc = sbias[0];
            #pragma unroll
            for (int kh = 0; kh < 3; kh++)
                #pragma unroll
                for (int kw = 0; kw < 3; kw++) {
                    float2 pv = sp[i + kh][j + kw];
                    acc += pv.x * swsr[(kh * 3 + kw) * 2]
                         + pv.y * swsr[(kh * 3 + kw) * 2 + 1];
                }
            x = 1.0f / (1.0f + __expf(-acc));
        }
        xm[i][j] = x;
    }
    __syncthreads();

    int cnt = 0;
    #pragma unroll
    for (int it = 0; it < 4; it++) {
        int l = t + it * 256;
        int i = l >> 5, j = l & 31;
        float accg = sbias[1], accb = sbias[2];
        #pragma unroll
        for (int kh = 0; kh < 3; kh++)
            #pragma unroll
            for (int kw = 0; kw < 3; kw++) {
                float xv = xm[i + kh][j + kw];
                accg += xv * swg[kh * 3 + kw];
                accb += xv * swb[kh * 3 + kw];
            }
        float x = xm[i + 1][j + 1];
        int m = (x > THRESH_) ? 1 : 0;
        int pixel = bbase + ((th + i) << 8) + tw + j;
        g_mask[pixel] = (unsigned char)m;
        g_gmap[pixel] = accg;
        g_bmap[pixel] = accb;
        cnt += m;
    }
    #pragma unroll
    for (int o = 16; o; o >>= 1) cnt += __shfl_xor_sync(0xFFFFFFFFu, cnt, o);
    int warp = t >> 5, lane = t & 31;
    if (lane == 0) scnt[warp] = cnt;
    __syncthreads();
    if (t == 0) {
        int s = 0;
        #pragma unroll
        for (int i = 0; i < 8; i++) s += scnt[i];
        atomicAdd(&g_counts[b], s);
    }
}

// ============================================================
// Kernel 3: moments — PER-WARP (64px) min-region compaction + gather.
// Warp w owns pixels [w*64, w*64+64) = exactly one pool block of g_tot.
// ============================================================
__global__ void moments_kernel(const float* __restrict__ in) {
    int r  = blockIdx.x;                 // chunk 0..127
    int b  = (B_ - 1) - blockIdx.y;      // reverse batch order
    int t  = threadIdx.x;
    int warp = t >> 5, lane = t & 31;
    int cbase = b * HW_ + r * 512;

    __shared__ unsigned char sflag[512];
    __shared__ unsigned short slist[512];
    __shared__ float4 r1[256], r2[256];
    __shared__ float4 st1[8][32], st2[8][32];
    __shared__ float4 ssel1[32], ssel2[32], stot1[32], stot2[32];

    // mask bytes -> smem
    if (t < 128) {
        uchar4 m4 = ((const uchar4*)(g_mask + cbase))[t];
        sflag[t * 4 + 0] = m4.x;
        sflag[t * 4 + 1] = m4.y;
        sflag[t * 4 + 2] = m4.z;
        sflag[t * 4 + 3] = m4.w;
    }
    __syncthreads();

    // ---- per-warp min-region selection + compaction ----
    int base_px = warp * 64;
    int f0 = sflag[base_px + lane];
    int f1 = sflag[base_px + 32 + lane];
    unsigned bal0 = __ballot_sync(0xFFFFFFFFu, f0);
    unsigned bal1 = __ballot_sync(0xFFFFFFFFu, f1);
    int ones = __popc(bal0) + __popc(bal1);
    int selb = (ones <= 32) ? 1 : 0;
    unsigned sb0 = selb ? bal0 : ~bal0;
    unsigned sb1 = selb ? bal1 : ~bal1;
    int n0 = __popc(sb0);
    int nselw = n0 + __popc(sb1);
    unsigned lmask = (1u << lane) - 1u;
    if ((sb0 >> lane) & 1) slist[base_px + __popc(sb0 & lmask)] = (unsigned short)(base_px + lane);
    if ((sb1 >> lane) & 1) slist[base_px + n0 + __popc(sb1 & lmask)] = (unsigned short)(base_px + 32 + lane);
    __syncwarp();

    // gather own warp's compacted list, MLP=4
    const float4* basep = ((const float4*)in) + (size_t)cbase * 32 + lane;
    float4 a1 = make_float4(0,0,0,0), a2 = make_float4(0,0,0,0);
    int i2 = 0;
    for (; i2 + 3 < nselw; i2 += 4) {
        int p0 = slist[base_px + i2];
        int p1 = slist[base_px + i2 + 1];
        int p2 = slist[base_px + i2 + 2];
        int p3 = slist[base_px + i2 + 3];
        float4 v0 = basep[(size_t)p0 * 32];
        float4 v1 = basep[(size_t)p1 * 32];
        float4 v2 = basep[(size_t)p2 * 32];
        float4 v3 = basep[(size_t)p3 * 32];
        a1.x += v0.x; a1.y += v0.y; a1.z += v0.z; a1.w += v0.w;
        a2.x += v0.x * v0.x; a2.y += v0.y * v0.y; a2.z += v0.z * v0.z; a2.w += v0.w * v0.w;
        a1.x += v1.x; a1.y += v1.y; a1.z += v1.z; a1.w += v1.w;
        a2.x += v1.x * v1.x; a2.y += v1.y * v1.y; a2.z += v1.z * v1.z; a2.w += v1.w * v1.w;
        a1.x += v2.x; a1.y += v2.y; a1.z += v2.z; a1.w += v2.w;
        a2.x += v2.x * v2.x; a2.y += v2.y * v2.y; a2.z += v2.z * v2.z; a2.w += v2.w * v2.w;
        a1.x += v3.x; a1.y += v3.y; a1.z += v3.z; a1.w += v3.w;
        a2.x += v3.x * v3.x; a2.y += v3.y * v3.y; a2.z += v3.z * v3.z; a2.w += v3.w * v3.w;
    }
    for (; i2 < nselw; i2++) {
        int p = slist[base_px + i2];
        float4 v = basep[(size_t)p * 32];
        a1.x += v.x; a1.y += v.y; a1.z += v.z; a1.w += v.w;
        a2.x += v.x * v.x; a2.y += v.y * v.y; a2.z += v.z * v.z; a2.w += v.w * v.w;
    }

    // per-warp totals (pool block aligned with this warp's 64 px)
    int pb = (cbase >> 6) + warp;
    float4 tw1 = g_tot1[pb * 32 + lane];
    float4 tw2 = g_tot2[pb * 32 + lane];
    float4 s1v, s2v;
    s1v.x = selb ? a1.x : (tw1.x - a1.x);
    s1v.y = selb ? a1.y : (tw1.y - a1.y);
    s1v.z = selb ? a1.z : (tw1.z - a1.z);
    s1v.w = selb ? a1.w : (tw1.w - a1.w);
    s2v.x = selb ? a2.x : (tw2.x - a2.x);
    s2v.y = selb ? a2.y : (tw2.y - a2.y);
    s2v.z = selb ? a2.z : (tw2.z - a2.z);
    s2v.w = selb ? a2.w : (tw2.w - a2.w);

    r1[t] = s1v; r2[t] = s2v;
    st1[warp][lane] = tw1; st2[warp][lane] = tw2;
    __syncthreads();

    // 4-way parallel 8-warp reductions
    if (t < 32) {
        float4 a = make_float4(0,0,0,0);
        #pragma unroll
        for (int w = 0; w < 8; w++) {
            float4 x = r1[w * 32 + t];
            a.x += x.x; a.y += x.y; a.z += x.z; a.w += x.w;
        }
        ssel1[t] = a;
    } else if (t < 64) {
        int c = t - 32;
        float4 a = make_float4(0,0,0,0);
        #pragma unroll
        for (int w = 0; w < 8; w++) {
            float4 x = r2[w * 32 + c];
            a.x += x.x; a.y += x.y; a.z += x.z; a.w += x.w;
        }
        ssel2[c] = a;
    } else if (t < 96) {
        int c = t - 64;
        float4 a = make_float4(0,0,0,0);
        #pragma unroll
        for (int w = 0; w < 8; w++) {
            float4 x = st1[w][c];
            a.x += x.x; a.y += x.y; a.z += x.z; a.w += x.w;
        }
        stot1[c] = a;
    } else if (t < 128) {
        int c = t - 96;
        float4 a = make_float4(0,0,0,0);
        #pragma unroll
        for (int w = 0; w < 8; w++) {
            float4 x = st2[w][c];
            a.x += x.x; a.y += x.y; a.z += x.z; a.w += x.w;
        }
        stot2[c] = a;
    }
    __syncthreads();

    // per-chunk partials: {s1v, s2v, s1tot, s2tot} per channel
    if (t < C_) {
        int c4 = t >> 2, k = t & 3;
        g_partials[((size_t)b * NBLK_ + r) * C_ + t] = make_float4(
            ((const float*)&ssel1[c4])[k],
            ((const float*)&ssel2[c4])[k],
            ((const float*)&stot1[c4])[k],
            ((const float*)&stot2[c4])[k]);
    }

    // ---- last block of this batch finalizes ----
    __shared__ int is_last;
    __threadfence();
    __syncthreads();
    if (t == 0) is_last = (atomicAdd(&g_done[b], 1) == NBLK_ - 1) ? 1 : 0;
    __syncthreads();
    if (!is_last) return;

    {
        int c    = t & 127;
        int half = t >> 7;
        const float4* pp = g_partials + (size_t)b * NBLK_ * C_ + (size_t)(half * 64) * C_ + c;
        float a1s = 0.f, a2s = 0.f, a3s = 0.f, a4s = 0.f;
        #pragma unroll 8
        for (int k = 0; k < 64; k++) {
            float4 p = pp[(size_t)k * C_];
            a1s += p.x; a2s += p.y; a3s += p.z; a4s += p.w;
        }
        r1[t] = make_float4(a1s, a2s, a3s, a4s);
    }
    __syncthreads();
    if (t < C_) {
        float4 lo = r1[t], hi = r1[t + 128];
        float s1v_ = lo.x + hi.x;
        float s2v_ = lo.y + hi.y;
        float s1_  = lo.z + hi.z;
        float s2_  = lo.w + hi.w;

        float cnt_v = (float)g_counts[b];
        float cnt_m = (float)HW_ - cnt_v;
        float s1m = s1_ - s1v_;
        float s2m = s2_ - s2v_;

        float fs_v  = cnt_v + EPS_;
        float mu_v  = s1v_ / fs_v;
        float var_v = (s2v_ - 2.f * mu_v * s1v_ + mu_v * mu_v * cnt_v) / fs_v;
        float is_v  = 1.0f / sqrtf(var_v + EPS_);
        float fs_m  = cnt_m + EPS_;
        float mu_m  = s1m / fs_m;
        float var_m = (s2m - 2.f * mu_m * s1m + mu_m * mu_m * cnt_m) / fs_m;
        float is_m  = 1.0f / sqrtf(var_m + EPS_);

        ((float2*)g_params)[((size_t)b * 2 + 1) * C_ + t] = make_float2(mu_v, is_v);
        ((float2*)g_params)[((size_t)b * 2 + 0) * C_ + t] = make_float2(mu_m, is_m);
    }
}

// ============================================================
// Kernel 4: apply — R4-identical smem-params version (32 regs, occ 88%).
// ============================================================
__global__ void apply_kernel(const float* __restrict__ in, float* __restrict__ out) {
    int t = threadIdx.x;
    size_t base = (size_t)blockIdx.x * 1024;
    int pix0 = blockIdx.x * 32;
    int b = pix0 >> 16;

    __shared__ float4 sparams[128];   // [region(2)][c4(32)][2]
    if (t < 128) sparams[t] = ((const float4*)g_params)[b * 128 + t];
    __syncthreads();

    const float4* in4 = (const float4*)in;
    float4* out4 = (float4*)out;

    float4 v[4];
    #pragma unroll
    for (int k = 0; k < 4; k++)
        v[k] = in4[base + t + 256 * k];

    #pragma unroll
    for (int k = 0; k < 4; k++) {
        int i4  = t + 256 * k;
        int pix = pix0 + (i4 >> 5);
        int c4  = i4 & 31;
        int m        = g_mask[pix];
        float beta   = g_bmap[pix];
        float gamma  = g_gmap[pix];
        float4 p0 = sparams[m * 64 + c4 * 2];
        float4 p1 = sparams[m * 64 + c4 * 2 + 1];
        float4 o;
        o.x = (v[k].x - p0.x) * p0.y * beta + gamma;
        o.y = (v[k].y - p0.z) * p0.w * beta + gamma;
        o.z = (v[k].z - p1.x) * p1.y * beta + gamma;
        o.w = (v[k].w - p1.z) * p1.w * beta + gamma;
        out4[base + i4] = o;
    }
}

// ============================================================
extern "C" void kernel_launch(void* const* d_in, const int* in_sizes, int n_in,
                              void* d_out, int out_size) {
    const float* in      = (const float*)d_in[0];
    const float* w_sr    = (const float*)d_in[1];
    const float* b_sr    = (const float*)d_in[2];
    const float* w_gamma = (const float*)d_in[3];
    const float* b_gamma = (const float*)d_in[4];
    const float* w_beta  = (const float*)d_in[5];
    const float* b_beta  = (const float*)d_in[6];
    float* out = (float*)d_out;

    pool_kernel<<<P_ / PBLK_, 256>>>(in);
    fused_conv_kernel<<<B_ * 64, 256>>>(w_sr, b_sr, w_gamma, b_gamma, w_beta, b_beta);
    moments_kernel<<<dim3(NBLK_, B_), 256>>>(in);
    apply_kernel<<<P_ / 32, 256>>>(in, out);
}